// round 16
// baseline (speedup 1.0000x reference)
#include <cuda_runtime.h>
#include <cuda_bf16.h>
#include <cstdint>

// Problem constants
#define BB    2
#define SS    2048
#define DD    1024
#define HH    16
#define DHh   64
#define FFD   4096
#define BSR   (BB*SS)          // 4096 rows
#define QC    512              // query-chunk rows per attention pass
#define NCHUNK (SS/QC)         // 4

// ---------------- static scratch (~304MB; lifetimes sequential) -------------
__device__ float g_Q  [BB*SS*DD];
__device__ float g_K  [BB*SS*DD];
__device__ float g_V  [BB*SS*DD];
__device__ float g_Vt [BB*HH*DHh*SS];      // V transposed [b*h][dh][S]
__device__ float g_Sc [BB*HH*QC*SS];       // 128 MB score chunk
__device__ float g_ctx[BB*SS*DD];
__device__ float g_ar [BB*SS*DD];
__device__ float g_y  [BB*SS*DD];
__device__ float g_h  [BB*SS*FFD];
__device__ float g_z  [BB*SS*DD];

// ================= bf16 split helpers (proven) =================
__device__ __forceinline__ void bsplit2(float x0, float x1, uint32_t& hp, uint32_t& lp)
{
    asm("cvt.rn.bf16x2.f32 %0, %1, %2;" : "=r"(hp) : "f"(x1), "f"(x0));
    float h0 = __uint_as_float(hp << 16);
    float h1 = __uint_as_float(hp & 0xffff0000u);
    float r0 = x0 - h0;
    float r1 = x1 - h1;
    asm("cvt.rn.bf16x2.f32 %0, %1, %2;" : "=r"(lp) : "f"(r1), "f"(r0));
}

__device__ __forceinline__ void mma16(float* d, const uint32_t* a, const uint32_t* b)
{
    asm volatile(
        "mma.sync.aligned.m16n8k16.row.col.f32.bf16.bf16.f32 "
        "{%0,%1,%2,%3},{%4,%5,%6,%7},{%8,%9},{%0,%1,%2,%3};"
        : "+f"(d[0]), "+f"(d[1]), "+f"(d[2]), "+f"(d[3])
        : "r"(a[0]), "r"(a[1]), "r"(a[2]), "r"(a[3]), "r"(b[0]), "r"(b[1]));
}

// ================= bf16-split NT GEMM, 256 threads, occupancy 2 =============
// C[M,N] = epilogue( alpha * A[M,K] @ B[N,K]^T ), fp32 in/out.
// 256 threads = 8 warps, warp grid (BM/WM)x(BN/WN) == 8. BK == 32.
// Identical mainloop math/layout to the proven 512-thread version; only the
// CTA shape changed (BN 128->64) so two CTAs co-reside per SM.
template<int BM,int BN,int BK,int WM,int WN,bool RELU,bool BIAS,bool RES>
__global__ __launch_bounds__(256,2)
void bgemm_k(const float* __restrict__ A, int lda,
             const float* __restrict__ Bm, int ldb,
             float*       __restrict__ C,  int ldc,
             int K, float alpha,
             const float* __restrict__ bias,
             const float* __restrict__ res,
             int zdiv,
             long soA, long siA, long soB, long siB, long soC, long siC)
{
    constexpr int SDP = BK/2 + 4;          // uint32 pairs per row (stride 20)
    constexpr int MT  = WM / 16;
    constexpr int NT2 = WN / 8;
    constexpr int MW  = BM / WM;
    constexpr int KV  = BK / 4;
    constexpr int NAc = (BM * KV) / 256;   // float4 chunks per thread, A (4)
    constexpr int NBc = (BN * KV) / 256;   // (2)

    __shared__ uint32_t sAh[BM*SDP], sAl[BM*SDP];
    __shared__ uint32_t sBh[BN*SDP], sBl[BN*SDP];

    const int z  = blockIdx.z;
    const long zo = z / zdiv, zi = z % zdiv;
    A  += zo*soA + zi*siA;
    Bm += zo*soB + zi*siB;
    C  += zo*soC + zi*siC;

    const int tid    = threadIdx.x;
    const int lane   = tid & 31;
    const int warpId = tid >> 5;
    const int wm     = warpId % MW;
    const int wn     = warpId / MW;
    const int r      = lane >> 2;
    const int c      = lane & 3;
    const int rowBase = blockIdx.y * BM;
    const int colBase = blockIdx.x * BN;

    int aR[NAc], aP[NAc];
    #pragma unroll
    for (int j = 0; j < NAc; j++) {
        int i = tid + j*256;
        aR[j] = i / KV;
        aP[j] = (i % KV) * 2;
    }
    int bR[NBc], bP[NBc];
    #pragma unroll
    for (int j = 0; j < NBc; j++) {
        int i = tid + j*256;
        bR[j] = i / KV;
        bP[j] = (i % KV) * 2;
    }

    float acc[MT][NT2][4];
    #pragma unroll
    for (int im = 0; im < MT; im++)
        #pragma unroll
        for (int in = 0; in < NT2; in++)
            #pragma unroll
            for (int q = 0; q < 4; q++) acc[im][in][q] = 0.f;

    float4 ra[NAc], rb[NBc];
    const int nT = K / BK;

    // ---- prologue: load + split-store tile 0 ----
    #pragma unroll
    for (int j = 0; j < NAc; j++)
        ra[j] = *(const float4*)(A + (long)(rowBase + aR[j])*lda + aP[j]*2);
    #pragma unroll
    for (int j = 0; j < NBc; j++)
        rb[j] = *(const float4*)(Bm + (long)(colBase + bR[j])*ldb + bP[j]*2);
    #pragma unroll
    for (int j = 0; j < NAc; j++) {
        uint32_t h0,l0,h1,l1;
        bsplit2(ra[j].x, ra[j].y, h0, l0);
        bsplit2(ra[j].z, ra[j].w, h1, l1);
        sAh[aR[j]*SDP + aP[j]    ] = h0;  sAl[aR[j]*SDP + aP[j]    ] = l0;
        sAh[aR[j]*SDP + aP[j] + 1] = h1;  sAl[aR[j]*SDP + aP[j] + 1] = l1;
    }
    #pragma unroll
    for (int j = 0; j < NBc; j++) {
        uint32_t h0,l0,h1,l1;
        bsplit2(rb[j].x, rb[j].y, h0, l0);
        bsplit2(rb[j].z, rb[j].w, h1, l1);
        sBh[bR[j]*SDP + bP[j]    ] = h0;  sBl[bR[j]*SDP + bP[j]    ] = l0;
        sBh[bR[j]*SDP + bP[j] + 1] = h1;  sBl[bR[j]*SDP + bP[j] + 1] = l1;
    }
    __syncthreads();

    for (int t = 0; t < nT; t++) {
        const bool has_next = (t + 1) < nT;
        if (has_next) {
            const int kn = (t + 1) * BK;
            #pragma unroll
            for (int j = 0; j < NAc; j++)
                ra[j] = *(const float4*)(A + (long)(rowBase + aR[j])*lda + (kn + aP[j]*2));
            #pragma unroll
            for (int j = 0; j < NBc; j++)
                rb[j] = *(const float4*)(Bm + (long)(colBase + bR[j])*ldb + (kn + bP[j]*2));
        }

        #pragma unroll
        for (int ks = 0; ks < BK/16; ks++) {
            const int pb = ks * 8;
            uint32_t afh[MT][4], afl[MT][4], bfh[NT2][2], bfl[NT2][2];
            #pragma unroll
            for (int im = 0; im < MT; im++) {
                const int mb = wm*WM + im*16;
                afh[im][0] = sAh[(mb+r  )*SDP + pb + c    ];
                afh[im][1] = sAh[(mb+r+8)*SDP + pb + c    ];
                afh[im][2] = sAh[(mb+r  )*SDP + pb + c + 4];
                afh[im][3] = sAh[(mb+r+8)*SDP + pb + c + 4];
                afl[im][0] = sAl[(mb+r  )*SDP + pb + c    ];
                afl[im][1] = sAl[(mb+r+8)*SDP + pb + c    ];
                afl[im][2] = sAl[(mb+r  )*SDP + pb + c + 4];
                afl[im][3] = sAl[(mb+r+8)*SDP + pb + c + 4];
            }
            #pragma unroll
            for (int in = 0; in < NT2; in++) {
                const int nb = wn*WN + in*8;
                bfh[in][0] = sBh[(nb+r)*SDP + pb + c    ];
                bfh[in][1] = sBh[(nb+r)*SDP + pb + c + 4];
                bfl[in][0] = sBl[(nb+r)*SDP + pb + c    ];
                bfl[in][1] = sBl[(nb+r)*SDP + pb + c + 4];
            }
            #pragma unroll
            for (int im = 0; im < MT; im++)
                #pragma unroll
                for (int in = 0; in < NT2; in++) {
                    mma16(acc[im][in], afh[im], bfh[in]);  // hi*hi
                    mma16(acc[im][in], afh[im], bfl[in]);  // hi*lo
                    mma16(acc[im][in], afl[im], bfh[in]);  // lo*hi
                }
        }
        __syncthreads();

        if (has_next) {
            #pragma unroll
            for (int j = 0; j < NAc; j++) {
                uint32_t h0,l0,h1,l1;
                bsplit2(ra[j].x, ra[j].y, h0, l0);
                bsplit2(ra[j].z, ra[j].w, h1, l1);
                sAh[aR[j]*SDP + aP[j]    ] = h0;  sAl[aR[j]*SDP + aP[j]    ] = l0;
                sAh[aR[j]*SDP + aP[j] + 1] = h1;  sAl[aR[j]*SDP + aP[j] + 1] = l1;
            }
            #pragma unroll
            for (int j = 0; j < NBc; j++) {
                uint32_t h0,l0,h1,l1;
                bsplit2(rb[j].x, rb[j].y, h0, l0);
                bsplit2(rb[j].z, rb[j].w, h1, l1);
                sBh[bR[j]*SDP + bP[j]    ] = h0;  sBl[bR[j]*SDP + bP[j]    ] = l0;
                sBh[bR[j]*SDP + bP[j] + 1] = h1;  sBl[bR[j]*SDP + bP[j] + 1] = l1;
            }
            __syncthreads();
        }
    }

    // ---- epilogue ----
    #pragma unroll
    for (int im = 0; im < MT; im++) {
        #pragma unroll
        for (int in = 0; in < NT2; in++) {
            const long row0 = rowBase + wm*WM + im*16 + r;
            const long row1 = row0 + 8;
            const int  col  = colBase + wn*WN + in*8 + 2*c;
            float2 d0 = make_float2(acc[im][in][0]*alpha, acc[im][in][1]*alpha);
            float2 d1 = make_float2(acc[im][in][2]*alpha, acc[im][in][3]*alpha);
            if (BIAS) {
                float2 bv = *(const float2*)(bias + col);
                d0.x += bv.x; d0.y += bv.y; d1.x += bv.x; d1.y += bv.y;
            }
            if (RES) {
                float2 r0 = *(const float2*)(res + row0*(long)ldc + col);
                float2 r1 = *(const float2*)(res + row1*(long)ldc + col);
                d0.x += r0.x; d0.y += r0.y; d1.x += r1.x; d1.y += r1.y;
            }
            if (RELU) {
                d0.x = fmaxf(d0.x, 0.f); d0.y = fmaxf(d0.y, 0.f);
                d1.x = fmaxf(d1.x, 0.f); d1.y = fmaxf(d1.y, 0.f);
            }
            *(float2*)(C + row0*(long)ldc + col) = d0;
            *(float2*)(C + row1*(long)ldc + col) = d1;
        }
    }
}

// ---------------- transpose V (fp32, exact): [B,S,H*64] -> [b*h][dh][S] -----
__global__ void vtrans_k(const float* __restrict__ V, float* __restrict__ Vt)
{
    __shared__ float t[32][33];
    const int bh = blockIdx.z;
    const int b  = bh / HH, h = bh % HH;
    const int s0 = blockIdx.x * 32;
    const int d0 = blockIdx.y * 32;
    const int tx = threadIdx.x, ty = threadIdx.y;

    #pragma unroll
    for (int i = ty; i < 32; i += 8)
        t[i][tx] = V[((long)(b*SS + s0 + i))*DD + h*DHh + d0 + tx];
    __syncthreads();
    #pragma unroll
    for (int i = ty; i < 32; i += 8)
        Vt[((long)bh*DHh + d0 + i)*SS + s0 + tx] = t[tx][i];
}

// ---------------- softmax over rows of length 2048 (input already relu'd) ----
__global__ void softmax_k(float* __restrict__ Sc)
{
    const long row = blockIdx.x;
    float* p = Sc + row * (long)SS;
    const int tid = threadIdx.x;
    float4 v0 = ((const float4*)p)[tid];
    float4 v1 = ((const float4*)p)[tid + 256];

    float m = fmaxf(fmaxf(fmaxf(v0.x,v0.y), fmaxf(v0.z,v0.w)),
                    fmaxf(fmaxf(v1.x,v1.y), fmaxf(v1.z,v1.w)));
    #pragma unroll
    for (int o = 16; o; o >>= 1) m = fmaxf(m, __shfl_xor_sync(0xffffffffu, m, o));

    __shared__ float smax[8], ssum[8];
    const int wid = tid >> 5, lid = tid & 31;
    if (lid == 0) smax[wid] = m;
    __syncthreads();
    m = smax[0];
    #pragma unroll
    for (int i = 1; i < 8; i++) m = fmaxf(m, smax[i]);

    float e[8];
    e[0]=__expf(v0.x-m); e[1]=__expf(v0.y-m); e[2]=__expf(v0.z-m); e[3]=__expf(v0.w-m);
    e[4]=__expf(v1.x-m); e[5]=__expf(v1.y-m); e[6]=__expf(v1.z-m); e[7]=__expf(v1.w-m);
    float s = ((e[0]+e[1])+(e[2]+e[3])) + ((e[4]+e[5])+(e[6]+e[7]));
    #pragma unroll
    for (int o = 16; o; o >>= 1) s += __shfl_xor_sync(0xffffffffu, s, o);
    if (lid == 0) ssum[wid] = s;
    __syncthreads();
    s = ssum[0];
    #pragma unroll
    for (int i = 1; i < 8; i++) s += ssum[i];

    const float inv = 1.0f / s;
    ((float4*)p)[tid]       = make_float4(e[0]*inv, e[1]*inv, e[2]*inv, e[3]*inv);
    ((float4*)p)[tid + 256] = make_float4(e[4]*inv, e[5]*inv, e[6]*inv, e[7]*inv);
}

// ---------------- layernorm over rows of length 1024 ----------------
__global__ void ln_k(const float* __restrict__ in, float* __restrict__ out,
                     const float* __restrict__ gw, const float* __restrict__ bw)
{
    const long row = blockIdx.x;
    const float* p = in + row * (long)DD;
    const int tid = threadIdx.x;
    float4 v = ((const float4*)p)[tid];
    float s = v.x + v.y + v.z + v.w;
    float q = v.x*v.x + v.y*v.y + v.z*v.z + v.w*v.w;
    #pragma unroll
    for (int o = 16; o; o >>= 1) {
        s += __shfl_xor_sync(0xffffffffu, s, o);
        q += __shfl_xor_sync(0xffffffffu, q, o);
    }
    __shared__ float ss[8], qq[8];
    const int wid = tid >> 5, lid = tid & 31;
    if (lid == 0) { ss[wid] = s; qq[wid] = q; }
    __syncthreads();
    float S = 0.f, Q = 0.f;
    #pragma unroll
    for (int i = 0; i < 8; i++) { S += ss[i]; Q += qq[i]; }

    const float mean = S * (1.0f / DD);
    const float var  = Q * (1.0f / DD) - mean * mean;
    const float inv  = rsqrtf(var + 1e-5f);

    float4 g4 = ((const float4*)gw)[tid];
    float4 b4 = ((const float4*)bw)[tid];
    float4 o;
    o.x = (v.x - mean) * inv * g4.x + b4.x;
    o.y = (v.y - mean) * inv * g4.y + b4.y;
    o.z = (v.z - mean) * inv * g4.z + b4.z;
    o.w = (v.w - mean) * inv * g4.w + b4.w;
    ((float4*)(out + row * (long)DD))[tid] = o;
}

// ---------------- launch ----------------
extern "C" void kernel_launch(void* const* d_in, const int* in_sizes, int n_in,
                              void* d_out, int out_size)
{
    const float* X   = (const float*)d_in[0];
    const float* Wq  = (const float*)d_in[1];
    const float* Wk  = (const float*)d_in[2];
    const float* Wo  = (const float*)d_in[3];
    const float* l1g = (const float*)d_in[4];
    const float* l1b = (const float*)d_in[5];
    const float* l2g = (const float*)d_in[6];
    const float* l2b = (const float*)d_in[7];
    const float* W1  = (const float*)d_in[8];
    const float* b1  = (const float*)d_in[9];
    const float* W2  = (const float*)d_in[10];
    const float* b2  = (const float*)d_in[11];
    float* out = (float*)d_out;

    float *Q, *K, *V, *Vt, *Sc, *CT, *AR, *Y, *Hh, *Z;
    cudaGetSymbolAddress((void**)&Q,  g_Q);
    cudaGetSymbolAddress((void**)&K,  g_K);
    cudaGetSymbolAddress((void**)&V,  g_V);
    cudaGetSymbolAddress((void**)&Vt, g_Vt);
    cudaGetSymbolAddress((void**)&Sc, g_Sc);
    cudaGetSymbolAddress((void**)&CT, g_ctx);
    cudaGetSymbolAddress((void**)&AR, g_ar);
    cudaGetSymbolAddress((void**)&Y,  g_y);
    cudaGetSymbolAddress((void**)&Hh, g_h);
    cudaGetSymbolAddress((void**)&Z,  g_z);

    const dim3 blk256(256);
    const dim3 gproj(DD/64,   BSR/128, 1);       // 16 x 32 = 512 CTAs
    const dim3 gscC (SS/64,   QC/128,  BB*HH);   // 32 x 4 x 32 = 4096 CTAs
    const dim3 gctxC(DHh/64,  QC/128,  BB*HH);   // 1 x 4 x 32 = 128 CTAs
    const dim3 gf1  (FFD/64,  BSR/128, 1);       // 64 x 32 = 2048 CTAs

    // --- QKV projections: Q/K = X@Wq^T / X@Wk^T, V = X@Wo^T ---
    bgemm_k<128,64,32,32,32,false,false,false><<<gproj, blk256>>>(
        X, DD, Wq, DD, Q, DD, DD, 1.f, nullptr, nullptr, 1, 0,0,0,0,0,0);
    bgemm_k<128,64,32,32,32,false,false,false><<<gproj, blk256>>>(
        X, DD, Wk, DD, K, DD, DD, 1.f, nullptr, nullptr, 1, 0,0,0,0,0,0);
    bgemm_k<128,64,32,32,32,false,false,false><<<gproj, blk256>>>(
        X, DD, Wo, DD, V, DD, DD, 1.f, nullptr, nullptr, 1, 0,0,0,0,0,0);

    // --- transpose V for NT ctx ---
    vtrans_k<<<dim3(SS/32, DHh/32, BB*HH), dim3(32,8)>>>(V, Vt);

    // --- attention, chunked over query rows ---
    for (int cch = 0; cch < NCHUNK; cch++) {
        // scores chunk: relu(Q[c] @ K^T / 8), batched over (b,h)
        bgemm_k<128,64,32,32,32,true,false,false><<<gscC, blk256>>>(
            Q + (long)cch*QC*DD, DD, K, DD, Sc, SS, DHh, 0.125f, nullptr, nullptr,
            HH, (long)SS*DD, (long)DHh,
                (long)SS*DD, (long)DHh,
                (long)HH*QC*SS, (long)QC*SS);

        softmax_k<<<BB*HH*QC, 256>>>(Sc);

        // ctx chunk = attn[QC,S] @ Vt[b*H+h][dh][S]^T
        bgemm_k<128,64,32,32,32,false,false,false><<<gctxC, blk256>>>(
            Sc, SS, Vt, SS, CT + (long)cch*QC*DD, DD, SS, 1.f, nullptr, nullptr,
            HH, (long)HH*QC*SS, (long)QC*SS,
                (long)HH*DHh*SS, (long)DHh*SS,
                (long)SS*DD, (long)DHh);
    }

    // --- out-proj + residual X ---
    bgemm_k<128,64,32,32,32,false,false,true><<<gproj, blk256>>>(
        CT, DD, Wo, DD, AR, DD, DD, 1.f, nullptr, X, 1, 0,0,0,0,0,0);

    ln_k<<<BSR, 256>>>(AR, Y, l1g, l1b);

    // --- FFN1: relu(y @ W1^T + b1) ---
    bgemm_k<128,64,32,32,32,true,true,false><<<gf1, blk256>>>(
        Y, DD, W1, DD, Hh, FFD, DD, 1.f, b1, nullptr, 1, 0,0,0,0,0,0);

    // --- FFN2: h @ W2^T + b2 + y ---
    bgemm_k<128,64,32,32,32,false,true,true><<<gproj, blk256>>>(
        Hh, FFD, W2, FFD, Z, DD, FFD, 1.f, b2, Y, 1, 0,0,0,0,0,0);

    ln_k<<<BSR, 256>>>(Z, out, l2g, l2b);
}